// round 1
// baseline (speedup 1.0000x reference)
#include <cuda_runtime.h>
#include <math.h>

// Problem constants (MoELayer_76433237999752)
#define TT 4096      // tokens = B*S = 2*2048
#define DM 1024      // d_model
#define DH 4096      // d_hidden
#define NE 8         // experts
#define TOPK 2

// ---------------------------------------------------------------------------
// Device-global scratch (sanctioned alternative to cudaMalloc).
// ---------------------------------------------------------------------------
__device__ int   g_cnt[NE];                    // tokens routed to each expert
__device__ int   g_base[NE];                   // exclusive prefix of g_cnt
__device__ int   g_tok[NE * TT];               // token index lists per expert
__device__ float g_wt [NE * TT];               // combine weights per expert
__device__ float g_h  [(size_t)TT * TOPK * DH]; // packed hidden activations (128 MB)

// ---------------------------------------------------------------------------
// Kernel 0: zero output accumulator + expert counters
// ---------------------------------------------------------------------------
__global__ void init_kernel(float* __restrict__ out_y) {
    int i = blockIdx.x * blockDim.x + threadIdx.x;
    if (i < NE) g_cnt[i] = 0;
    size_t stride = (size_t)gridDim.x * blockDim.x;
    for (size_t j = i; j < (size_t)TT * DM; j += stride) out_y[j] = 0.0f;
}

// ---------------------------------------------------------------------------
// Kernel 1: gating — logits, top-2, softmax, expert list append
// One warp per token.
// ---------------------------------------------------------------------------
__global__ void gate_kernel(const float* __restrict__ x,
                            const float* __restrict__ Wg,
                            const float* __restrict__ bg,
                            float* __restrict__ logits_out,
                            int write_logits) {
    int gwarp = (blockIdx.x * blockDim.x + threadIdx.x) >> 5;
    int lane  = threadIdx.x & 31;
    if (gwarp >= TT) return;

    const float* xr = x + (size_t)gwarp * DM;
    float acc[NE];
#pragma unroll
    for (int e = 0; e < NE; e++) acc[e] = 0.0f;

    for (int d = lane; d < DM; d += 32) {
        float xv = xr[d];
        const float* wr = Wg + (size_t)d * NE;
#pragma unroll
        for (int e = 0; e < NE; e++) acc[e] += xv * wr[e];
    }
#pragma unroll
    for (int e = 0; e < NE; e++) {
#pragma unroll
        for (int o = 16; o > 0; o >>= 1)
            acc[e] += __shfl_xor_sync(0xffffffffu, acc[e], o);
    }

    if (lane == 0) {
#pragma unroll
        for (int e = 0; e < NE; e++) acc[e] += bg[e];
        if (write_logits) {
#pragma unroll
            for (int e = 0; e < NE; e++)
                logits_out[(size_t)gwarp * NE + e] = acc[e];
        }
        // top-2 (ties: lower index wins, matching jax.lax.top_k)
        int i0 = 0; float v0 = acc[0];
#pragma unroll
        for (int e = 1; e < NE; e++) { if (acc[e] > v0) { v0 = acc[e]; i0 = e; } }
        int i1 = -1; float v1 = -INFINITY;
#pragma unroll
        for (int e = 0; e < NE; e++) {
            if (e == i0) continue;
            if (acc[e] > v1) { v1 = acc[e]; i1 = e; }
        }
        // softmax over [v0, v1], v0 >= v1
        float ew = expf(v1 - v0);
        float inv = 1.0f / (1.0f + ew);
        float w0 = inv;
        float w1 = ew * inv;

        int s0 = atomicAdd(&g_cnt[i0], 1);
        g_tok[i0 * TT + s0] = gwarp;
        g_wt [i0 * TT + s0] = w0;
        int s1 = atomicAdd(&g_cnt[i1], 1);
        g_tok[i1 * TT + s1] = gwarp;
        g_wt [i1 * TT + s1] = w1;
    }
}

// ---------------------------------------------------------------------------
// Kernel 2: tiny exclusive prefix over 8 counts
// ---------------------------------------------------------------------------
__global__ void prefix_kernel() {
    if (threadIdx.x == 0) {
        int s = 0;
#pragma unroll
        for (int e = 0; e < NE; e++) { g_base[e] = s; s += g_cnt[e]; }
    }
}

// ---------------------------------------------------------------------------
// GEMM tiles: BM=BN=128, BK=8, 256 threads, 8x8 per thread, fp32 FFMA.
// ---------------------------------------------------------------------------

// GEMM1: h[base+r, :] = relu( x[tok[r], :] @ W1[e] + b1[e] )
__global__ void __launch_bounds__(256, 2)
gemm1_kernel(const float* __restrict__ x,
             const float* __restrict__ W1,
             const float* __restrict__ b1) {
    int e   = blockIdx.z;
    int cnt = g_cnt[e];
    int rb  = blockIdx.y * 128;
    if (rb >= cnt) return;
    int nb  = blockIdx.x * 128;

    const float* Bw  = W1 + (size_t)e * DM * DH;
    const float* b1e = b1 + (size_t)e * DH;
    const int*   toks = g_tok + e * TT;
    int base = g_base[e];

    __shared__ float As[8][128];
    __shared__ float Bs[8][128];

    int tid = threadIdx.x;
    int tx = tid & 15, ty = tid >> 4;

    float acc[8][8];
#pragma unroll
    for (int i = 0; i < 8; i++)
#pragma unroll
        for (int j = 0; j < 8; j++) acc[i][j] = 0.0f;

    int ar = tid >> 1;             // A tile row this thread loads
    int ak = (tid & 1) * 4;        // k offset (0 or 4)
    int arow = rb + ar;
    bool avalid = arow < cnt;
    const float* aptr = avalid ? (x + (size_t)toks[arow] * DM + ak) : x;

    int bkr = tid >> 5;            // B tile k row
    int bnc = (tid & 31) * 4;      // B tile n col
    const float* bptr = Bw + (size_t)bkr * DH + nb + bnc;

    for (int kt = 0; kt < DM; kt += 8) {
        float4 av = avalid ? *(const float4*)(aptr + kt)
                           : make_float4(0.f, 0.f, 0.f, 0.f);
        As[ak + 0][ar] = av.x;
        As[ak + 1][ar] = av.y;
        As[ak + 2][ar] = av.z;
        As[ak + 3][ar] = av.w;
        float4 bv = *(const float4*)(bptr + (size_t)kt * DH);
        *(float4*)&Bs[bkr][bnc] = bv;
        __syncthreads();
#pragma unroll
        for (int k = 0; k < 8; k++) {
            float a[8], b[8];
            *(float4*)(a)     = *(const float4*)&As[k][ty * 8];
            *(float4*)(a + 4) = *(const float4*)&As[k][ty * 8 + 4];
            *(float4*)(b)     = *(const float4*)&Bs[k][tx * 8];
            *(float4*)(b + 4) = *(const float4*)&Bs[k][tx * 8 + 4];
#pragma unroll
            for (int i = 0; i < 8; i++)
#pragma unroll
                for (int j = 0; j < 8; j++) acc[i][j] += a[i] * b[j];
        }
        __syncthreads();
    }

    float* hbase = g_h + (size_t)base * DH;
#pragma unroll
    for (int i = 0; i < 8; i++) {
        int r = rb + ty * 8 + i;
        if (r >= cnt) break;
        float* hr = hbase + (size_t)r * DH + nb + tx * 8;
#pragma unroll
        for (int j = 0; j < 8; j++) {
            float v = acc[i][j] + b1e[nb + tx * 8 + j];
            hr[j] = v > 0.0f ? v : 0.0f;
        }
    }
}

// GEMM2: out[tok[r], :] += w[r] * ( h[base+r, :] @ W2[e] + b2[e] )
__global__ void __launch_bounds__(256, 2)
gemm2_kernel(const float* __restrict__ W2,
             const float* __restrict__ b2,
             float* __restrict__ out) {
    int e   = blockIdx.z;
    int cnt = g_cnt[e];
    int rb  = blockIdx.y * 128;
    if (rb >= cnt) return;
    int nb  = blockIdx.x * 128;

    const float* Bw  = W2 + (size_t)e * DH * DM;
    const float* b2e = b2 + (size_t)e * DM;
    int base = g_base[e];
    const float* A = g_h + (size_t)base * DH;

    __shared__ float As[8][128];
    __shared__ float Bs[8][128];

    int tid = threadIdx.x;
    int tx = tid & 15, ty = tid >> 4;

    float acc[8][8];
#pragma unroll
    for (int i = 0; i < 8; i++)
#pragma unroll
        for (int j = 0; j < 8; j++) acc[i][j] = 0.0f;

    int ar = tid >> 1;
    int ak = (tid & 1) * 4;
    int arow = rb + ar;
    bool avalid = arow < cnt;
    const float* aptr = avalid ? (A + (size_t)arow * DH + ak) : A;

    int bkr = tid >> 5;
    int bnc = (tid & 31) * 4;
    const float* bptr = Bw + (size_t)bkr * DM + nb + bnc;

    for (int kt = 0; kt < DH; kt += 8) {
        float4 av = avalid ? *(const float4*)(aptr + kt)
                           : make_float4(0.f, 0.f, 0.f, 0.f);
        As[ak + 0][ar] = av.x;
        As[ak + 1][ar] = av.y;
        As[ak + 2][ar] = av.z;
        As[ak + 3][ar] = av.w;
        float4 bv = *(const float4*)(bptr + (size_t)kt * DM);
        *(float4*)&Bs[bkr][bnc] = bv;
        __syncthreads();
#pragma unroll
        for (int k = 0; k < 8; k++) {
            float a[8], b[8];
            *(float4*)(a)     = *(const float4*)&As[k][ty * 8];
            *(float4*)(a + 4) = *(const float4*)&As[k][ty * 8 + 4];
            *(float4*)(b)     = *(const float4*)&Bs[k][tx * 8];
            *(float4*)(b + 4) = *(const float4*)&Bs[k][tx * 8 + 4];
#pragma unroll
            for (int i = 0; i < 8; i++)
#pragma unroll
                for (int j = 0; j < 8; j++) acc[i][j] += a[i] * b[j];
        }
        __syncthreads();
    }

    const int* toks = g_tok + e * TT;
    const float* wts = g_wt + e * TT;
#pragma unroll
    for (int i = 0; i < 8; i++) {
        int r = rb + ty * 8 + i;
        if (r >= cnt) break;
        int   token = toks[r];
        float w     = wts[r];
        float* orow = out + (size_t)token * DM + nb + tx * 8;
#pragma unroll
        for (int j = 0; j < 8; j++) {
            float v = w * (acc[i][j] + b2e[nb + tx * 8 + j]);
            atomicAdd(&orow[j], v);
        }
    }
}

// ---------------------------------------------------------------------------
// Launch
// ---------------------------------------------------------------------------
extern "C" void kernel_launch(void* const* d_in, const int* in_sizes, int n_in,
                              void* d_out, int out_size) {
    const float* x  = (const float*)d_in[0];
    const float* Wg = (const float*)d_in[1];
    const float* bg = (const float*)d_in[2];
    const float* W1 = (const float*)d_in[3];
    const float* b1 = (const float*)d_in[4];
    const float* W2 = (const float*)d_in[5];
    const float* b2 = (const float*)d_in[6];

    float* out_y = (float*)d_out;
    int write_logits = (out_size >= TT * (DM + NE)) ? 1 : 0;
    float* logits = out_y + (size_t)TT * DM;

    init_kernel<<<256, 256>>>(out_y);
    gate_kernel<<<(TT * 32 + 255) / 256, 256>>>(x, Wg, bg, logits, write_logits);
    prefix_kernel<<<1, 32>>>();

    dim3 g1(DH / 128, TT / 128, NE);   // (32, 32, 8); empty row-blocks early-exit
    gemm1_kernel<<<g1, 256>>>(x, W1, b1);

    dim3 g2(DM / 128, TT / 128, NE);   // (8, 32, 8)
    gemm2_kernel<<<g2, 256>>>(W2, b2, out_y);
}

// round 3
// speedup vs baseline: 2.6635x; 2.6635x over previous
#include <cuda_runtime.h>
#include <cuda_bf16.h>
#include <cstdint>
#include <math.h>

// Problem constants (MoELayer_76433237999752)
#define TT 4096      // tokens = B*S
#define DM 1024      // d_model
#define DH 4096      // d_hidden
#define NE 8         // experts
#define RTOT (TT*2)  // total routed rows (top-2)
#define HPAD 128     // row padding so GEMM2 A-tile reads never go OOB

// GEMM tiling
#define BM 128
#define BN 128
#define BK 32
#define AROW 40      // padded A row length in bf16 elems (80 B = 5*16, conflict-free)
#define BROW 136     // padded B row length in bf16 elems (272 B = 17*16, conflict-free)

// ===========================================================================
// Device-global scratch
// ===========================================================================
__device__ int   g_cnt [NE];
__device__ int   g_base[NE];
__device__ int   g_tok [NE * TT];            // per-expert token lists
__device__ int   g_te  [TT * 2];             // per-token expert ids
__device__ int   g_ts  [TT * 2];             // per-token slot in expert list
__device__ float g_tw  [TT * 2];             // per-token combine weights
__device__ __nv_bfloat16 g_h_hi[(size_t)(RTOT + HPAD) * DH];
__device__ __nv_bfloat16 g_h_lo[(size_t)(RTOT + HPAD) * DH];
__device__ float         g_yp  [(size_t)RTOT * DM];   // unscaled expert outputs

// ===========================================================================
// Inline PTX helpers (all plain sm_80-era PTX — no "a"-gated features)
// ===========================================================================
__device__ __forceinline__ uint32_t smem_u32(const void* p) {
    uint32_t a;
    asm("{ .reg .u64 t; cvta.to.shared.u64 t, %1; cvt.u32.u64 %0, t; }" : "=r"(a) : "l"(p));
    return a;
}
__device__ __forceinline__ void ldsm_x4(uint32_t* r, uint32_t addr) {
    asm volatile("ldmatrix.sync.aligned.m8n8.x4.shared.b16 {%0,%1,%2,%3}, [%4];"
                 : "=r"(r[0]), "=r"(r[1]), "=r"(r[2]), "=r"(r[3]) : "r"(addr));
}
__device__ __forceinline__ void ldsm_x2t(uint32_t* r, uint32_t addr) {
    asm volatile("ldmatrix.sync.aligned.m8n8.x2.trans.shared.b16 {%0,%1}, [%2];"
                 : "=r"(r[0]), "=r"(r[1]) : "r"(addr));
}
__device__ __forceinline__ void mma16816(float* c, const uint32_t* a, const uint32_t* b) {
    asm volatile("mma.sync.aligned.m16n8k16.row.col.f32.bf16.bf16.f32 "
                 "{%0,%1,%2,%3}, {%4,%5,%6,%7}, {%8,%9}, {%0,%1,%2,%3};"
                 : "+f"(c[0]), "+f"(c[1]), "+f"(c[2]), "+f"(c[3])
                 : "r"(a[0]), "r"(a[1]), "r"(a[2]), "r"(a[3]), "r"(b[0]), "r"(b[1]));
}

// fp32 -> bf16 hi/lo splits
__device__ __forceinline__ void split4(float4 v, uint2& h, uint2& l) {
    __nv_bfloat162 h0 = __float22bfloat162_rn(make_float2(v.x, v.y));
    __nv_bfloat162 h1 = __float22bfloat162_rn(make_float2(v.z, v.w));
    float2 f0 = __bfloat1622float2(h0), f1 = __bfloat1622float2(h1);
    __nv_bfloat162 l0 = __float22bfloat162_rn(make_float2(v.x - f0.x, v.y - f0.y));
    __nv_bfloat162 l1 = __float22bfloat162_rn(make_float2(v.z - f1.x, v.w - f1.y));
    h = make_uint2(*(uint32_t*)&h0, *(uint32_t*)&h1);
    l = make_uint2(*(uint32_t*)&l0, *(uint32_t*)&l1);
}
__device__ __forceinline__ void split2(float v0, float v1, uint32_t& h, uint32_t& l) {
    __nv_bfloat162 hb = __float22bfloat162_rn(make_float2(v0, v1));
    float2 hf = __bfloat1622float2(hb);
    __nv_bfloat162 lb = __float22bfloat162_rn(make_float2(v0 - hf.x, v1 - hf.y));
    h = *(uint32_t*)&hb;
    l = *(uint32_t*)&lb;
}

// ===========================================================================
// Routing kernels
// ===========================================================================
__global__ void zero_cnt_kernel() {
    if (threadIdx.x < NE) g_cnt[threadIdx.x] = 0;
}

__global__ void gate_kernel(const float* __restrict__ x,
                            const float* __restrict__ Wg,
                            const float* __restrict__ bg,
                            float* __restrict__ logits_out,
                            int write_logits) {
    int t    = (blockIdx.x * blockDim.x + threadIdx.x) >> 5;
    int lane = threadIdx.x & 31;
    if (t >= TT) return;

    const float* xr = x + (size_t)t * DM;
    float acc[NE];
#pragma unroll
    for (int e = 0; e < NE; e++) acc[e] = 0.0f;
    for (int d = lane; d < DM; d += 32) {
        float xv = xr[d];
        const float* wr = Wg + (size_t)d * NE;
#pragma unroll
        for (int e = 0; e < NE; e++) acc[e] += xv * wr[e];
    }
#pragma unroll
    for (int e = 0; e < NE; e++)
#pragma unroll
        for (int o = 16; o > 0; o >>= 1)
            acc[e] += __shfl_xor_sync(0xffffffffu, acc[e], o);

    if (lane == 0) {
#pragma unroll
        for (int e = 0; e < NE; e++) acc[e] += bg[e];
        if (write_logits)
#pragma unroll
            for (int e = 0; e < NE; e++)
                logits_out[(size_t)t * NE + e] = acc[e];
        int i0 = 0; float v0 = acc[0];
#pragma unroll
        for (int e = 1; e < NE; e++) if (acc[e] > v0) { v0 = acc[e]; i0 = e; }
        int i1 = -1; float v1 = -INFINITY;
#pragma unroll
        for (int e = 0; e < NE; e++) {
            if (e == i0) continue;
            if (acc[e] > v1) { v1 = acc[e]; i1 = e; }
        }
        float ew  = expf(v1 - v0);
        float inv = 1.0f / (1.0f + ew);

        int s0 = atomicAdd(&g_cnt[i0], 1);
        g_tok[i0 * TT + s0] = t;
        int s1 = atomicAdd(&g_cnt[i1], 1);
        g_tok[i1 * TT + s1] = t;

        g_te[2*t]   = i0; g_ts[2*t]   = s0; g_tw[2*t]   = inv;
        g_te[2*t+1] = i1; g_ts[2*t+1] = s1; g_tw[2*t+1] = ew * inv;
    }
}

__global__ void prefix_kernel() {
    if (threadIdx.x == 0) {
        int s = 0;
#pragma unroll
        for (int e = 0; e < NE; e++) { g_base[e] = s; s += g_cnt[e]; }
    }
}

// ===========================================================================
// GEMM1: h[base+r] = relu( x[tok[r]] @ W1[e] + b1[e] ), h stored bf16 hi/lo
// 128x128 tile, BK=32, 8 warps (2x4), warp tile 64x32, bf16 mma 3-pass.
// ===========================================================================
__global__ void __launch_bounds__(256)
moe_gemm1(const float* __restrict__ x, const float* __restrict__ W1,
          const float* __restrict__ b1) {
    int e   = blockIdx.z;
    int cnt = g_cnt[e];
    int rb  = blockIdx.y * BM;
    if (rb >= cnt) return;
    int nb   = blockIdx.x * BN;
    int base = g_base[e];
    const float* We = W1 + (size_t)e * DM * DH;

    __shared__ __align__(16) __nv_bfloat16 sAh[BM * AROW];
    __shared__ __align__(16) __nv_bfloat16 sAl[BM * AROW];
    __shared__ __align__(16) __nv_bfloat16 sBh[BK * BROW];
    __shared__ __align__(16) __nv_bfloat16 sBl[BK * BROW];

    int tid  = threadIdx.x;
    int lane = tid & 31, wid = tid >> 5;
    int wm = wid >> 2, wn = wid & 3;           // warp: (wm*64, wn*32)

    // ---- global load mapping ----
    int arow = tid >> 1;                        // A: 2 threads per row
    bool avalid = (rb + arow) < cnt;
    int tok = g_tok[e * TT + (avalid ? rb + arow : rb)];
    const float* aPtr = x + (size_t)tok * DM + 16 * (tid & 1);
    int kr = tid >> 3;                          // B: k-row
    const float* bPtr = We + (size_t)kr * DH + nb + 4 * (tid & 7);

    // ---- SMEM store offsets (bytes) ----
    uint32_t sAhB = smem_u32(sAh), sAlB = smem_u32(sAl);
    uint32_t sBhB = smem_u32(sBh), sBlB = smem_u32(sBl);
    uint32_t aSt = (uint32_t)arow * 80 + (tid & 1) * 32;   // + i*8
    uint32_t bSt = (uint32_t)kr * 272 + (tid & 7) * 8;     // + i*64

    // ---- ldmatrix addresses ----
    uint32_t aHiA = sAhB + ((uint32_t)(wm*64 + (lane&7) + ((lane>>3)&1)*8)) * 80
                        + (lane >> 4) * 16;
    uint32_t aLoA = aHiA + (sAlB - sAhB);
    uint32_t bHiA = sBhB + (uint32_t)(lane & 15) * 272 + wn * 64;
    uint32_t bLoA = bHiA + (sBlB - sBhB);

    float cacc[4][4][4];
#pragma unroll
    for (int mi = 0; mi < 4; mi++)
#pragma unroll
        for (int ni = 0; ni < 4; ni++)
#pragma unroll
            for (int q = 0; q < 4; q++) cacc[mi][ni][q] = 0.0f;

    const int NC = DM / BK;   // 32
    float4 av[4], bv[4];
#pragma unroll
    for (int i = 0; i < 4; i++) {
        av[i] = avalid ? *(const float4*)(aPtr + 4 * i)
                       : make_float4(0.f, 0.f, 0.f, 0.f);
        bv[i] = *(const float4*)(bPtr + 32 * i);
    }

    for (int kt = 0; kt < NC; kt++) {
        // store prefetched tile
#pragma unroll
        for (int i = 0; i < 4; i++) {
            uint2 h, l;
            split4(av[i], h, l);
            *(uint2*)((char*)sAh + aSt + i * 8) = h;
            *(uint2*)((char*)sAl + aSt + i * 8) = l;
            split4(bv[i], h, l);
            *(uint2*)((char*)sBh + bSt + i * 64) = h;
            *(uint2*)((char*)sBl + bSt + i * 64) = l;
        }
        __syncthreads();
        // prefetch next
        if (kt + 1 < NC) {
#pragma unroll
            for (int i = 0; i < 4; i++) {
                av[i] = avalid ? *(const float4*)(aPtr + (kt + 1) * 32 + 4 * i)
                               : make_float4(0.f, 0.f, 0.f, 0.f);
                bv[i] = *(const float4*)(bPtr + (size_t)(kt + 1) * 32 * DH + 32 * i);
            }
        }
        // mma over the 2 k16 steps of this BK=32 chunk
#pragma unroll
        for (int k16 = 0; k16 < 2; k16++) {
            uint32_t ah[4][4], al[4][4], bh[4][2], bl[4][2];
#pragma unroll
            for (int mi = 0; mi < 4; mi++) {
                ldsm_x4(ah[mi], aHiA + mi * 1280 + k16 * 32);
                ldsm_x4(al[mi], aLoA + mi * 1280 + k16 * 32);
            }
#pragma unroll
            for (int ni = 0; ni < 4; ni++) {
                ldsm_x2t(bh[ni], bHiA + ni * 16 + k16 * 4352);
                ldsm_x2t(bl[ni], bLoA + ni * 16 + k16 * 4352);
            }
#pragma unroll
            for (int mi = 0; mi < 4; mi++)
#pragma unroll
                for (int ni = 0; ni < 4; ni++) {
                    mma16816(cacc[mi][ni], ah[mi], bh[ni]);
                    mma16816(cacc[mi][ni], ah[mi], bl[ni]);
                    mma16816(cacc[mi][ni], al[mi], bh[ni]);
                }
        }
        __syncthreads();
    }

    // ---- epilogue: +bias, relu, bf16 hi/lo split, store h ----
    const float* bb = b1 + (size_t)e * DH + nb;
    int er = wm * 64 + (lane >> 2);
    int ec = wn * 32 + (lane & 3) * 2;
#pragma unroll
    for (int mi = 0; mi < 4; mi++) {
#pragma unroll
        for (int rr = 0; rr < 2; rr++) {
            int m = er + mi * 16 + rr * 8;
            if (rb + m >= cnt) continue;
            size_t rowoff = (size_t)(base + rb + m) * DH + nb;
#pragma unroll
            for (int ni = 0; ni < 4; ni++) {
                int c = ec + ni * 8;
                float v0 = cacc[mi][ni][rr * 2 + 0] + bb[c];
                float v1 = cacc[mi][ni][rr * 2 + 1] + bb[c + 1];
                v0 = v0 > 0.f ? v0 : 0.f;
                v1 = v1 > 0.f ? v1 : 0.f;
                uint32_t h, l;
                split2(v0, v1, h, l);
                *(uint32_t*)(g_h_hi + rowoff + c) = h;
                *(uint32_t*)(g_h_lo + rowoff + c) = l;
            }
        }
    }
}

// ===========================================================================
// GEMM2: yp[base+r] = h[base+r] @ W2[e] + b2[e]
// ===========================================================================
__global__ void __launch_bounds__(256)
moe_gemm2(const float* __restrict__ W2, const float* __restrict__ b2) {
    int e   = blockIdx.z;
    int cnt = g_cnt[e];
    int rb  = blockIdx.y * BM;
    if (rb >= cnt) return;
    int nb   = blockIdx.x * BN;
    int base = g_base[e];
    const float* We = W2 + (size_t)e * DH * DM;

    __shared__ __align__(16) __nv_bfloat16 sAh[BM * AROW];
    __shared__ __align__(16) __nv_bfloat16 sAl[BM * AROW];
    __shared__ __align__(16) __nv_bfloat16 sBh[BK * BROW];
    __shared__ __align__(16) __nv_bfloat16 sBl[BK * BROW];

    int tid  = threadIdx.x;
    int lane = tid & 31, wid = tid >> 5;
    int wm = wid >> 2, wn = wid & 3;

    int arow = tid >> 1;
    const __nv_bfloat16* ahPtr = g_h_hi + (size_t)(base + rb + arow) * DH + 16 * (tid & 1);
    const __nv_bfloat16* alPtr = g_h_lo + (size_t)(base + rb + arow) * DH + 16 * (tid & 1);
    int kr = tid >> 3;
    const float* bPtr = We + (size_t)kr * DM + nb + 4 * (tid & 7);

    uint32_t sAhB = smem_u32(sAh), sAlB = smem_u32(sAl);
    uint32_t sBhB = smem_u32(sBh), sBlB = smem_u32(sBl);
    uint32_t aSt = (uint32_t)arow * 80 + (tid & 1) * 32;   // + i*16 (uint4)
    uint32_t bSt = (uint32_t)kr * 272 + (tid & 7) * 8;

    uint32_t aHiA = sAhB + ((uint32_t)(wm*64 + (lane&7) + ((lane>>3)&1)*8)) * 80
                        + (lane >> 4) * 16;
    uint32_t aLoA = aHiA + (sAlB - sAhB);
    uint32_t bHiA = sBhB + (uint32_t)(lane & 15) * 272 + wn * 64;
    uint32_t bLoA = bHiA + (sBlB - sBhB);

    float cacc[4][4][4];
#pragma unroll
    for (int mi = 0; mi < 4; mi++)
#pragma unroll
        for (int ni = 0; ni < 4; ni++)
#pragma unroll
            for (int q = 0; q < 4; q++) cacc[mi][ni][q] = 0.0f;

    const int NC = DH / BK;   // 128
    uint4 ahv[2], alv[2];
    float4 bv[4];
#pragma unroll
    for (int i = 0; i < 2; i++) {
        ahv[i] = *(const uint4*)(ahPtr + 8 * i);
        alv[i] = *(const uint4*)(alPtr + 8 * i);
    }
#pragma unroll
    for (int i = 0; i < 4; i++) bv[i] = *(const float4*)(bPtr + 32 * i);

    for (int kt = 0; kt < NC; kt++) {
#pragma unroll
        for (int i = 0; i < 2; i++) {
            *(uint4*)((char*)sAh + aSt + i * 16) = ahv[i];
            *(uint4*)((char*)sAl + aSt + i * 16) = alv[i];
        }
#pragma unroll
        for (int i = 0; i < 4; i++) {
            uint2 h, l;
            split4(bv[i], h, l);
            *(uint2*)((char*)sBh + bSt + i * 64) = h;
            *(uint2*)((char*)sBl + bSt + i * 64) = l;
        }
        __syncthreads();
        if (kt + 1 < NC) {
#pragma unroll
            for (int i = 0; i < 2; i++) {
                ahv[i] = *(const uint4*)(ahPtr + (kt + 1) * 32 + 8 * i);
                alv[i] = *(const uint4*)(alPtr + (kt + 1) * 32 + 8 * i);
            }
#pragma unroll
            for (int i = 0; i < 4; i++)
                bv[i] = *(const float4*)(bPtr + (size_t)(kt + 1) * 32 * DM + 32 * i);
        }
#pragma unroll
        for (int k16 = 0; k16 < 2; k16++) {
            uint32_t ah[4][4], al[4][4], bh[4][2], bl[4][2];
#pragma unroll
            for (int mi = 0; mi < 4; mi++) {
                ldsm_x4(ah[mi], aHiA + mi * 1280 + k16 * 32);
                ldsm_x4(al[mi], aLoA + mi * 1280 + k16 * 32);
            }
#pragma unroll
            for (int ni = 0; ni < 4; ni++) {
                ldsm_x2t(bh[ni], bHiA + ni * 16 + k16 * 4352);
                ldsm_x2t(bl[ni], bLoA + ni * 16 + k16 * 4352);
            }
#pragma unroll
            for (int mi = 0; mi < 4; mi++)
#pragma unroll
                for (int ni = 0; ni < 4; ni++) {
                    mma16816(cacc[mi][ni], ah[mi], bh[ni]);
                    mma16816(cacc[mi][ni], ah[mi], bl[ni]);
                    mma16816(cacc[mi][ni], al[mi], bh[ni]);
                }
        }
        __syncthreads();
    }

    const float* bb = b2 + (size_t)e * DM + nb;
    int er = wm * 64 + (lane >> 2);
    int ec = wn * 32 + (lane & 3) * 2;
#pragma unroll
    for (int mi = 0; mi < 4; mi++) {
#pragma unroll
        for (int rr = 0; rr < 2; rr++) {
            int m = er + mi * 16 + rr * 8;
            if (rb + m >= cnt) continue;
            float* yrow = g_yp + (size_t)(base + rb + m) * DM + nb;
#pragma unroll
            for (int ni = 0; ni < 4; ni++) {
                int c = ec + ni * 8;
                float2 o;
                o.x = cacc[mi][ni][rr * 2 + 0] + bb[c];
                o.y = cacc[mi][ni][rr * 2 + 1] + bb[c + 1];
                *(float2*)(yrow + c) = o;
            }
        }
    }
}

// ===========================================================================
// combine: out[t] = w0*yp[r0] + w1*yp[r1]
// ===========================================================================
__global__ void combine_kernel(float* __restrict__ out) {
    int t = blockIdx.x;
    int c = threadIdx.x;   // float4 index; DM/4 == 256 == blockDim
    int e0 = g_te[2*t],   e1 = g_te[2*t+1];
    int r0 = g_base[e0] + g_ts[2*t];
    int r1 = g_base[e1] + g_ts[2*t+1];
    float w0 = g_tw[2*t], w1 = g_tw[2*t+1];
    float4 a = ((const float4*)(g_yp + (size_t)r0 * DM))[c];
    float4 b = ((const float4*)(g_yp + (size_t)r1 * DM))[c];
    float4 o;
    o.x = w0 * a.x + w1 * b.x;
    o.y = w0 * a.y + w1 * b.y;
    o.z = w0 * a.z + w1 * b.z;
    o.w = w0 * a.w + w1 * b.w;
    ((float4*)(out + (size_t)t * DM))[c] = o;
}

// ===========================================================================
// Launch
// ===========================================================================
extern "C" void kernel_launch(void* const* d_in, const int* in_sizes, int n_in,
                              void* d_out, int out_size) {
    const float* x  = (const float*)d_in[0];
    const float* Wg = (const float*)d_in[1];
    const float* bg = (const float*)d_in[2];
    const float* W1 = (const float*)d_in[3];
    const float* b1 = (const float*)d_in[4];
    const float* W2 = (const float*)d_in[5];
    const float* b2 = (const float*)d_in[6];

    float* out_y = (float*)d_out;
    int write_logits = (out_size >= TT * (DM + NE)) ? 1 : 0;
    float* logits = out_y + (size_t)TT * DM;

    zero_cnt_kernel<<<1, 32>>>();
    gate_kernel<<<(TT * 32) / 256, 256>>>(x, Wg, bg, logits, write_logits);
    prefix_kernel<<<1, 32>>>();

    moe_gemm1<<<dim3(DH / BN, TT / BM, NE), 256>>>(x, W1, b1);
    moe_gemm2<<<dim3(DM / BN, TT / BM, NE), 256>>>(W2, b2);

    combine_kernel<<<TT, DM / 4>>>(out_y);
}